// round 9
// baseline (speedup 1.0000x reference)
#include <cuda_runtime.h>
#include <cuda_bf16.h>
#include <cstdint>

// Holt-Winters additive triple smoothing (gamma unused; season static):
//   out[b,0] = series[b,0] + init_trend
//   sea_t    = init_season[(t - shift_b) mod SLEN]
//   smooth'  = alpha*(y_t - sea_t) + (1-alpha)*(smooth + trend)
//   trend'   = beta*(smooth' - smooth) + (1-beta)*trend
//   out[b,t] = smooth' + trend' + sea_t
//
// R9: (a) 1 row/thread, 32-row single-warp blocks, 2048 blocks -> ~14
// warps/SM single wave (2x the memory streams of R8); (b) season values
// pre-rotated into registers; chunk bodies templated on the compile-time
// season phase (32*ch mod 12 cycles 0,8,4), eliminating all per-step
// season LDS (bank-conflicted) and index ALU.

constexpr int ROWS    = 32;   // rows per block
constexpr int THREADS = 32;   // one warp
constexpr int C       = 32;   // time-steps per chunk
constexpr int CH4     = C / 4;        // 8
constexpr int S       = 36;   // smem row stride (floats)
constexpr int NCH     = 16;   // 512 / 32

__device__ __forceinline__ uint32_t smem_u32(const void* p) {
    return (uint32_t)__cvta_generic_to_shared(p);
}
__device__ __forceinline__ void cp_async16(uint32_t dst, const void* src) {
    asm volatile("cp.async.cg.shared.global [%0], [%1], 16;\n"
                 :: "r"(dst), "l"(src) : "memory");
}
__device__ __forceinline__ void cp_commit() {
    asm volatile("cp.async.commit_group;\n" ::: "memory");
}
template <int N>
__device__ __forceinline__ void cp_wait() {
    asm volatile("cp.async.wait_group %0;\n" :: "n"(N) : "memory");
}

__device__ __forceinline__ float hw_step(float y, float sea,
                                         float& smooth, float& trend,
                                         float alpha, float oma,
                                         float beta, float omb)
{
    float sn = alpha * (y - sea) + oma * (smooth + trend);
    float tn = beta * (sn - smooth) + omb * trend;
    smooth = sn;
    trend  = tn;
    return sn + tn + sea;
}

// One chunk: wait for its staged tile, kick prefetch of the next, run 32
// steps with compile-time season phase PH, stage outputs, store coalesced.
template<int PH, bool FIRST>
__device__ __forceinline__ void process_chunk(
    int ch, int lane, int row0,
    const float* __restrict__ series, float4* __restrict__ dstv,
    float (&s_in)[2][ROWS * S], float* __restrict__ s_out,
    float& smooth, float& trend, const float (&q)[12],
    float alpha, float oma, float beta, float omb, float init_trend,
    int T, int t4)
{
    const int buf = ch & 1;

    cp_wait<0>();    // chunk ch's tile landed
    __syncwarp();    // cross-lane visibility; retires prior reads of buf^1

    // prefetch chunk ch+1 into the other buffer (flies during compute/store)
    if (ch + 1 < NCH) {
        const float* src = series + (size_t)(ch + 1) * C;
        #pragma unroll
        for (int k = 0; k < (ROWS * CH4) / THREADS; ++k) {
            int qq = k * THREADS + lane;
            int r  = qq >> 3;
            int f4 = qq & 7;
            cp_async16(smem_u32(&s_in[buf ^ 1][r * S + f4 * 4]),
                       src + (size_t)(row0 + r) * T + f4 * 4);
        }
    }
    cp_commit();

    // compute: thread lane owns row lane; all season refs are static regs
    {
        const float4* rin  = (const float4*)(s_in[buf] + lane * S);
        float4*       rout = (float4*)(s_out + lane * S);
        #pragma unroll
        for (int g = 0; g < CH4; ++g) {
            float4 a = rin[g];
            float4 o;
            if (FIRST && g == 0) {
                smooth = a.x;
                trend  = init_trend;
                o.x = smooth + trend;
            } else {
                o.x = hw_step(a.x, q[(PH + g * 4 + 0) % 12], smooth, trend,
                              alpha, oma, beta, omb);
            }
            o.y = hw_step(a.y, q[(PH + g * 4 + 1) % 12], smooth, trend,
                          alpha, oma, beta, omb);
            o.z = hw_step(a.z, q[(PH + g * 4 + 2) % 12], smooth, trend,
                          alpha, oma, beta, omb);
            o.w = hw_step(a.w, q[(PH + g * 4 + 3) % 12], smooth, trend,
                          alpha, oma, beta, omb);
            rout[g] = o;
        }
    }
    __syncwarp();    // s_out complete across lanes

    // store: quarter-warp = one row's 128B line (coalesced STG.128)
    #pragma unroll
    for (int k = 0; k < (ROWS * CH4) / THREADS; ++k) {
        int qq = k * THREADS + lane;
        int r  = qq >> 3;
        int f4 = qq & 7;
        const float4* p = (const float4*)(s_out + r * S) + f4;
        dstv[(size_t)(row0 + r) * t4 + ch * CH4 + f4] = *p;
    }
    // next chunk's top __syncwarp orders these s_out reads before overwrite
}

__global__ __launch_bounds__(THREADS)
void hw_kernel(const float* __restrict__ series,
               const int*   __restrict__ shifts,
               const float* __restrict__ alpha_p,
               const float* __restrict__ beta_p,
               const float* __restrict__ season_g,
               const float* __restrict__ init_trend_p,
               float* __restrict__ out,
               int B, int T)
{
    __shared__ float s_in [2][ROWS * S];  // 2 x 4608 B
    __shared__ float s_out[ROWS * S];     //     4608 B

    const int lane = threadIdx.x;
    const int row0 = blockIdx.x * ROWS;

    const float alpha      = *alpha_p;
    const float beta       = *beta_p;
    const float init_trend = *init_trend_p;
    const float oma = 1.0f - alpha;
    const float omb = 1.0f - beta;

    // pre-rotated season registers: step t (>=1) uses q[t mod 12]
    //   q[j] = season[(j - shift) mod 12]
    int shift = shifts[row0 + lane];
    int m = (-shift) % 12; if (m < 0) m += 12;
    float q[12];
    #pragma unroll
    for (int j = 0; j < 12; ++j) {
        q[j] = season_g[m];
        m = (m + 1 == 12) ? 0 : m + 1;
    }

    const int t4 = T >> 2;
    float4* __restrict__ dstv = (float4*)out;

    float smooth = 0.0f, trend = 0.0f;

    // prologue: prefetch chunk 0 into buf 0 (coalesced 128B lines)
    #pragma unroll
    for (int k = 0; k < (ROWS * CH4) / THREADS; ++k) {
        int qq = k * THREADS + lane;
        int r  = qq >> 3;
        int f4 = qq & 7;
        cp_async16(smem_u32(&s_in[0][r * S + f4 * 4]),
                   series + (size_t)(row0 + r) * T + f4 * 4);
    }
    cp_commit();

    // chunk 0: phase 0, contains the t=0 special case
    process_chunk<0, true>(0, lane, row0, series, dstv, s_in, s_out,
                           smooth, trend, q, alpha, oma, beta, omb,
                           init_trend, T, t4);

    // chunks 1..15: season phase (32*ch mod 12) cycles 8, 4, 0
    #pragma unroll 1
    for (int c = 1; c < NCH; c += 3) {
        process_chunk<8, false>(c,     lane, row0, series, dstv, s_in, s_out,
                                smooth, trend, q, alpha, oma, beta, omb,
                                init_trend, T, t4);
        process_chunk<4, false>(c + 1, lane, row0, series, dstv, s_in, s_out,
                                smooth, trend, q, alpha, oma, beta, omb,
                                init_trend, T, t4);
        process_chunk<0, false>(c + 2, lane, row0, series, dstv, s_in, s_out,
                                smooth, trend, q, alpha, oma, beta, omb,
                                init_trend, T, t4);
    }
}

// Generic fallback (shape-safe): one thread per row, used only if the
// specialized shape assumptions (T%32==0, slen==12, B%32==0) don't hold.
__global__ __launch_bounds__(256)
void hw_kernel_generic(const float* __restrict__ series,
                       const int*   __restrict__ shifts,
                       const float* __restrict__ alpha_p,
                       const float* __restrict__ beta_p,
                       const float* __restrict__ season_g,
                       const float* __restrict__ init_trend_p,
                       float* __restrict__ out,
                       int B, int T, int slen)
{
    int row = blockIdx.x * blockDim.x + threadIdx.x;
    if (row >= B) return;
    const float alpha = *alpha_p, beta = *beta_p;
    const float oma = 1.0f - alpha, omb = 1.0f - beta;
    int shift = shifts[row];
    int idx = (1 - shift) % slen; if (idx < 0) idx += slen;
    const float* src = series + (size_t)row * T;
    float* dst = out + (size_t)row * T;
    float smooth = src[0], trend = *init_trend_p;
    dst[0] = smooth + trend;
    for (int t = 1; t < T; ++t) {
        float sea = season_g[idx];
        idx = (idx + 1 == slen) ? 0 : idx + 1;
        dst[t] = hw_step(src[t], sea, smooth, trend, alpha, oma, beta, omb);
    }
}

extern "C" void kernel_launch(void* const* d_in, const int* in_sizes, int n_in,
                              void* d_out, int out_size)
{
    // 0: series f32 [B*T]   1: shifts i32 [B]   2: alpha   3: beta
    // 4: gamma (unused)     5: init_season [SLEN]   6: init_trend   7: n_preds
    const float* series     = (const float*)d_in[0];
    const int*   shifts     = (const int*)  d_in[1];
    const float* alpha_p    = (const float*)d_in[2];
    const float* beta_p     = (const float*)d_in[3];
    const float* season     = (const float*)d_in[5];
    const float* init_trend = (const float*)d_in[6];
    float* out = (float*)d_out;

    int B    = in_sizes[1];
    int T    = in_sizes[0] / B;      // 512
    int slen = in_sizes[5];          // 12

    if (slen == 12 && T == 512 && (B % ROWS) == 0) {
        int blocks = B / ROWS;       // 2048
        hw_kernel<<<blocks, THREADS>>>(series, shifts, alpha_p, beta_p,
                                       season, init_trend, out, B, T);
    } else {
        int threads = 256;
        int blocks  = (B + threads - 1) / threads;
        hw_kernel_generic<<<blocks, threads>>>(series, shifts, alpha_p, beta_p,
                                               season, init_trend, out,
                                               B, T, slen);
    }
}